// round 1
// baseline (speedup 1.0000x reference)
#include <cuda_runtime.h>
#include <math.h>

// ---------------- problem constants ----------------
// x: (2,256,96,96); q/kv grid 48x48; heads g=8, d=32
#define NN 2
#define CC 256
#define HH 96
#define WW 96
#define HS 48            // h = w = 48
#define PP 2304          // HS*HS
#define COLS 4608        // NN*PP
#define GG 8
#define DD 32
#define NDIFF 95

// ---------------- scratch (device globals; no allocation) ----------------
__device__ float g_xs[CC * COLS];          // subsampled x, [c][n*2304+p]
__device__ float g_wqkv[3 * CC * CC];      // [768][256]
__device__ float g_qkv[3 * CC * COLS];     // rows 0..255 q, 256..511 k, 512..767 v
__device__ float g_px[NDIFF * CC];         // pos_x per diff, per channel (incl 1/sqrt2)
__device__ float g_py[NDIFF * CC];
__device__ float g_ex[16 * PP * 48];       // exp(ex - rowmax), [ng][q][v]
__device__ float g_ey[16 * PP * 48];       // exp(ey - rowmax), [ng][q][u]
__device__ float g_ek[16 * PP];            // raw ek then exp(ek - max) in place
__device__ float g_wt[16 * 48 * DD * 48];  // [ng][u][d][v] = EK[u,v]*V[d,u,v]
__device__ float g_zinv[16 * PP];
__device__ float g_att[CC * COLS];         // attention out, [c][n*2304+q]
__device__ float g_proj[CC * COLS];        // Wp @ att (bias added later)

// ---------------- small prep kernels ----------------
__global__ void k_concat_w(const float* __restrict__ Wq, const float* __restrict__ Wk,
                           const float* __restrict__ Wv) {
    int i = blockIdx.x * 256 + threadIdx.x;
    if (i < CC * CC) {
        g_wqkv[i] = Wq[i];
        g_wqkv[CC * CC + i] = Wk[i];
        g_wqkv[2 * CC * CC + i] = Wv[i];
    }
}

__global__ void k_sub(const float* __restrict__ x) {
    int i = blockIdx.x * 256 + threadIdx.x;  // over CC*COLS
    int c = i / COLS;
    int col = i % COLS;
    int n = col / PP;
    int p = col % PP;
    int ph = p / HS, pw = p % HS;
    g_xs[i] = x[((n * CC + c) * HH + ph * 2) * WW + pw * 2];
}

// pos projections: for each diff index (0..94), channel o:
// PX[dl][o] = (1/sqrt2) * sum_f basis(diff)[f] * Wx[o][f]
__global__ void k_pos(const float* __restrict__ Wx, const float* __restrict__ Wy) {
    __shared__ float basis[128];
    int dl = blockIdx.x;                 // 0..94
    float Dv = 2.0f * (float)(dl - 47);  // actual coordinate diff
    int t = threadIdx.x;
    if (t < 128) {
        int f = t & 63;
        float m = powf(1000.0f, (float)f * (1.0f / 64.0f));
        float a = Dv / m;
        basis[t] = (t < 64) ? sinf(a) : cosf(a);
    }
    __syncthreads();
    float sx = 0.f, sy = 0.f;
    const float* wxr = Wx + t * 128;
    const float* wyr = Wy + t * 128;
#pragma unroll 8
    for (int f = 0; f < 128; f++) {
        sx += basis[f] * wxr[f];
        sy += basis[f] * wyr[f];
    }
    const float is2 = 0.70710678118654752f;
    g_px[dl * CC + t] = sx * is2;
    g_py[dl * CC + t] = sy * is2;
}

// ---------------- SGEMM: C[Mx4608] = A[Mx256] @ B[256x4608] ----------------
__device__ __forceinline__ void sgemm_body(const float* __restrict__ A,
                                           const float* __restrict__ B,
                                           float* __restrict__ C) {
    __shared__ float As[8][128];
    __shared__ float Bs[8][128];
    int t = threadIdx.x;
    int bx = blockIdx.x, by = blockIdx.y;
    int tx = t % 16, ty = t / 16;
    int a_m = t >> 1;
    int a_k = (t & 1) * 4;
    int b_k = t >> 5;
    int b_n = (t & 31) * 4;
    const float* Ap = A + (by * 128 + a_m) * 256 + a_k;
    const float* Bp = B + b_k * COLS + bx * 128 + b_n;
    float acc[8][8];
#pragma unroll
    for (int i = 0; i < 8; i++)
#pragma unroll
        for (int j = 0; j < 8; j++) acc[i][j] = 0.f;

    for (int k0 = 0; k0 < 256; k0 += 8) {
        float4 av = *(const float4*)(Ap + k0);
        As[a_k + 0][a_m] = av.x;
        As[a_k + 1][a_m] = av.y;
        As[a_k + 2][a_m] = av.z;
        As[a_k + 3][a_m] = av.w;
        *(float4*)&Bs[b_k][b_n] = *(const float4*)(Bp + (size_t)k0 * COLS);
        __syncthreads();
#pragma unroll
        for (int k = 0; k < 8; k++) {
            float4 a0 = *(float4*)&As[k][ty * 4];
            float4 a1 = *(float4*)&As[k][64 + ty * 4];
            float4 b0 = *(float4*)&Bs[k][tx * 4];
            float4 b1 = *(float4*)&Bs[k][64 + tx * 4];
            float ar[8] = {a0.x, a0.y, a0.z, a0.w, a1.x, a1.y, a1.z, a1.w};
            float br[8] = {b0.x, b0.y, b0.z, b0.w, b1.x, b1.y, b1.z, b1.w};
#pragma unroll
            for (int i = 0; i < 8; i++)
#pragma unroll
                for (int j = 0; j < 8; j++) acc[i][j] += ar[i] * br[j];
        }
        __syncthreads();
    }
#pragma unroll
    for (int i = 0; i < 8; i++) {
        int row = by * 128 + ((i < 4) ? (ty * 4 + i) : (64 + ty * 4 + i - 4));
        float4 o0 = {acc[i][0], acc[i][1], acc[i][2], acc[i][3]};
        float4 o1 = {acc[i][4], acc[i][5], acc[i][6], acc[i][7]};
        *(float4*)(C + (size_t)row * COLS + bx * 128 + tx * 4) = o0;
        *(float4*)(C + (size_t)row * COLS + bx * 128 + 64 + tx * 4) = o1;
    }
}

__global__ void __launch_bounds__(256) k_sgemm_qkv() { sgemm_body(g_wqkv, g_xs, g_qkv); }
__global__ void __launch_bounds__(256) k_sgemm_wp(const float* __restrict__ Wp) {
    sgemm_body(Wp, g_att, g_proj);
}

// ---------------- ex/ey: per (n,g,h) row of 48 queries ----------------
__global__ void __launch_bounds__(256) k_exy() {
    int b = blockIdx.x;  // (ng)*48 + h
    int h = b % HS;
    int ng = b / HS;
    int g = ng % GG, n = ng / GG;
    __shared__ float qs[48][33];
    __shared__ float pxs[95][33];
    __shared__ float pys[48][33];
    __shared__ float exm[48][49];
    __shared__ float eym[48][49];
    __shared__ float rmx[48], rmy[48];
    int t = threadIdx.x;
    for (int i = t; i < 48 * 32; i += 256) {
        int d = i / 48, w_ = i % 48;
        qs[w_][d] = g_qkv[(size_t)(g * DD + d) * COLS + n * PP + h * HS + w_];
    }
    for (int i = t; i < 95 * 32; i += 256) {
        int dl = i / 32, d = i % 32;
        pxs[dl][d] = g_px[dl * CC + g * DD + d];
    }
    for (int i = t; i < 48 * 32; i += 256) {
        int u = i / 32, d = i % 32;
        pys[u][d] = g_py[(h - u + 47) * CC + g * DD + d];
    }
    __syncthreads();
    for (int i = t; i < PP; i += 256) {
        int w_ = i / 48, v = i % 48;
        float s = 0.f, s2 = 0.f;
#pragma unroll
        for (int d = 0; d < 32; d++) {
            float qv = qs[w_][d];
            s += qv * pxs[w_ - v + 47][d];
            s2 += qv * pys[v][d];  // v plays the role of u here
        }
        exm[w_][v] = s;
        eym[w_][v] = s2;
    }
    __syncthreads();
    if (t < 48) {
        float m = -1e30f;
        for (int v = 0; v < 48; v++) m = fmaxf(m, exm[t][v]);
        rmx[t] = m;
    } else if (t < 96) {
        int w_ = t - 48;
        float m = -1e30f;
        for (int u = 0; u < 48; u++) m = fmaxf(m, eym[w_][u]);
        rmy[w_] = m;
    }
    __syncthreads();
    for (int i = t; i < PP; i += 256) {
        int w_ = i / 48, v = i % 48;
        size_t base = ((size_t)ng * PP + h * HS + w_) * 48;
        g_ex[base + v] = expf(exm[w_][v] - rmx[w_]);
        g_ey[base + v] = expf(eym[w_][v] - rmy[w_]);
    }
}

// ---------------- ek + exp ----------------
__global__ void k_ek(const float* __restrict__ ab) {
    int i = blockIdx.x * 256 + threadIdx.x;  // 16*2304
    int ng = i / PP;
    int uv = i % PP;
    int g = ng % GG, n = ng / GG;
    float s = 0.f;
#pragma unroll
    for (int d = 0; d < 32; d++)
        s += ab[g * DD + d] * g_qkv[(size_t)(CC + g * DD + d) * COLS + n * PP + uv];
    g_ek[i] = s;
}

__global__ void k_ekmax() {
    __shared__ float red[256];
    int ng = blockIdx.x;
    int t = threadIdx.x;
    size_t base = (size_t)ng * PP;
    float m = -1e30f;
    for (int i = t; i < PP; i += 256) m = fmaxf(m, g_ek[base + i]);
    red[t] = m;
    __syncthreads();
    for (int s = 128; s > 0; s >>= 1) {
        if (t < s) red[t] = fmaxf(red[t], red[t + s]);
        __syncthreads();
    }
    float mk = red[0];
    for (int i = t; i < PP; i += 256) g_ek[base + i] = expf(g_ek[base + i] - mk);
}

// ---------------- Wt[ng][u][d][v] = EK[ng][u*48+v] * V[d, u*48+v] ----------------
__global__ void k_wt() {
    int i = blockIdx.x * 256 + threadIdx.x;  // 16*48*32*48
    int v = i % 48;
    int d = (i / 48) % 32;
    int u = (i / 1536) % 48;
    int ng = i / 73728;
    int g = ng % GG, n = ng / GG;
    g_wt[i] = g_ek[(size_t)ng * PP + u * 48 + v] *
              g_qkv[(size_t)(2 * CC + g * DD + d) * COLS + n * PP + u * 48 + v];
}

// ---------------- Z ----------------
__global__ void __launch_bounds__(256) k_z() {
    __shared__ float eks[PP];
    int ng = blockIdx.x;
    int q = blockIdx.y * 256 + threadIdx.x;
    for (int i = threadIdx.x; i < PP; i += 256) eks[i] = g_ek[(size_t)ng * PP + i];
    __syncthreads();
    size_t base = ((size_t)ng * PP + q) * 48;
    float exr[48];
#pragma unroll
    for (int v = 0; v < 48; v++) exr[v] = g_ex[base + v];
    float z = 0.f;
    for (int u = 0; u < 48; u++) {
        float su = 0.f;
#pragma unroll
        for (int v = 0; v < 48; v++) su += eks[u * 48 + v] * exr[v];
        z += g_ey[base + u] * su;
    }
    g_zinv[(size_t)ng * PP + q] = 1.0f / z;
}

// ---------------- fused attention numerator + normalize ----------------
// block: 128 threads; tile: d=32 x q=128 for one (ng, qtile)
// acc[d][q] = sum_u Ey[q][u] * sum_v Wt[ng][u][d][v] * Ex[q][v]
__global__ void __launch_bounds__(128) k_attn() {
    extern __shared__ float sm[];
    float* Exs = sm;           // [v][q] : 48*128
    float* Eys = sm + 6144;    // [u][q] : 48*128
    float* Ws = sm + 12288;    // [d][v] padded stride 49 : 32*49
    int ng = blockIdx.y;
    int q0 = blockIdx.x * 128;
    int t = threadIdx.x;
    int qlane = t % 16;
    int dgrp = t / 16;  // 0..7 -> d = dgrp*4 + dd
    for (int i = t; i < 128 * 48; i += 128) {
        int q = i / 48, v = i % 48;
        size_t gb = ((size_t)ng * PP + q0 + q) * 48 + v;
        Exs[v * 128 + q] = g_ex[gb];
        Eys[v * 128 + q] = g_ey[gb];
    }
    __syncthreads();
    float acc[8][4];
#pragma unroll
    for (int a = 0; a < 8; a++)
#pragma unroll
        for (int b = 0; b < 4; b++) acc[a][b] = 0.f;

    const float* wbase = g_wt + (size_t)ng * 48 * 1536;
    for (int u = 0; u < 48; u++) {
        const float4* src = (const float4*)(wbase + u * 1536);
        for (int j = t; j < 384; j += 128) {
            float4 w4 = src[j];
            int L = j * 4;
            int d = L / 48, v = L % 48;
            Ws[d * 49 + v + 0] = w4.x;
            Ws[d * 49 + v + 1] = w4.y;
            Ws[d * 49 + v + 2] = w4.z;
            Ws[d * 49 + v + 3] = w4.w;
        }
        __syncthreads();
        float eyv[8];
#pragma unroll
        for (int qq = 0; qq < 8; qq++) eyv[qq] = Eys[u * 128 + qq * 16 + qlane];
        float tmp[8][4];
#pragma unroll
        for (int a = 0; a < 8; a++)
#pragma unroll
            for (int b = 0; b < 4; b++) tmp[a][b] = 0.f;
#pragma unroll 8
        for (int v = 0; v < 48; v++) {
            float wr0 = Ws[(dgrp * 4 + 0) * 49 + v];
            float wr1 = Ws[(dgrp * 4 + 1) * 49 + v];
            float wr2 = Ws[(dgrp * 4 + 2) * 49 + v];
            float wr3 = Ws[(dgrp * 4 + 3) * 49 + v];
#pragma unroll
            for (int qq = 0; qq < 8; qq++) {
                float ex = Exs[v * 128 + qq * 16 + qlane];
                tmp[qq][0] += wr0 * ex;
                tmp[qq][1] += wr1 * ex;
                tmp[qq][2] += wr2 * ex;
                tmp[qq][3] += wr3 * ex;
            }
        }
#pragma unroll
        for (int qq = 0; qq < 8; qq++)
#pragma unroll
            for (int dd = 0; dd < 4; dd++) acc[qq][dd] += eyv[qq] * tmp[qq][dd];
        __syncthreads();
    }
    int g = ng % GG, n = ng / GG;
#pragma unroll
    for (int qq = 0; qq < 8; qq++) {
        int q = q0 + qq * 16 + qlane;
        float zi = g_zinv[(size_t)ng * PP + q];
#pragma unroll
        for (int dd = 0; dd < 4; dd++) {
            int d = dgrp * 4 + dd;
            g_att[(size_t)(g * DD + d) * COLS + n * PP + q] = acc[qq][dd] * zi;
        }
    }
}

// ---------------- bilinear 48->96 upsample + bias + gamma residual ----------------
__device__ __forceinline__ void taps48(int o, int& i0, int& i1, float& w0, float& w1) {
    int tt = o >> 1;
    if ((o & 1) == 0) {
        if (tt == 0) { i0 = 0; i1 = 0; w0 = 1.f; w1 = 0.f; }
        else { i0 = tt - 1; i1 = tt; w0 = 0.25f; w1 = 0.75f; }
    } else {
        if (tt == 47) { i0 = 47; i1 = 47; w0 = 1.f; w1 = 0.f; }
        else { i0 = tt; i1 = tt + 1; w0 = 0.75f; w1 = 0.25f; }
    }
}

__global__ void k_final(const float* __restrict__ x, const float* __restrict__ bp,
                        const float* __restrict__ gamma, float* __restrict__ out) {
    int i = blockIdx.x * 256 + threadIdx.x;  // over NN*CC*HH*WW
    int j = i % WW;
    int r = (i / WW) % HH;
    int c = (i / (HH * WW)) % CC;
    int n = i / (CC * HH * WW);
    int r0, r1, c0, c1;
    float rw0, rw1, cw0, cw1;
    taps48(r, r0, r1, rw0, rw1);
    taps48(j, c0, c1, cw0, cw1);
    const float* pr = g_proj + (size_t)c * COLS + n * PP;
    float v00 = pr[r0 * HS + c0], v01 = pr[r0 * HS + c1];
    float v10 = pr[r1 * HS + c0], v11 = pr[r1 * HS + c1];
    float bi = rw0 * (cw0 * v00 + cw1 * v01) + rw1 * (cw0 * v10 + cw1 * v11);
    out[i] = gamma[0] * (bi + bp[c]) + x[i];
}

// ---------------- launch ----------------
extern "C" void kernel_launch(void* const* d_in, const int* in_sizes, int n_in,
                              void* d_out, int out_size) {
    (void)in_sizes; (void)n_in; (void)out_size;
    const float* x = (const float*)d_in[0];
    const float* Wq = (const float*)d_in[1];
    const float* Wk = (const float*)d_in[2];
    const float* Wv = (const float*)d_in[3];
    const float* Wx = (const float*)d_in[4];
    const float* Wy = (const float*)d_in[5];
    const float* ab = (const float*)d_in[6];
    const float* Wp = (const float*)d_in[7];
    const float* bp = (const float*)d_in[8];
    const float* gamma = (const float*)d_in[9];
    float* out = (float*)d_out;

    // 55424 B dynamic smem for k_attn (set every call; first call is uncaptured)
    cudaFuncSetAttribute(k_attn, cudaFuncAttributeMaxDynamicSharedMemorySize, 55424);

    k_concat_w<<<256, 256>>>(Wq, Wk, Wv);
    k_sub<<<(CC * COLS) / 256, 256>>>(x);
    k_sgemm_qkv<<<dim3(36, 6), 256>>>();
    k_pos<<<95, 256>>>(Wx, Wy);
    k_exy<<<16 * HS, 256>>>();
    k_ek<<<(16 * PP) / 256, 256>>>(ab);
    k_ekmax<<<16, 256>>>();
    k_wt<<<(16 * 48 * DD * 48) / 256, 256>>>();
    k_z<<<dim3(16, PP / 256), 256>>>();
    k_attn<<<dim3(PP / 128, 16), 128, 55424>>>();
    k_sgemm_wp<<<dim3(36, 2), 256>>>(Wp);
    k_final<<<(NN * CC * HH * WW) / 256, 256>>>(x, bp, gamma, out);
}